// round 5
// baseline (speedup 1.0000x reference)
#include <cuda_runtime.h>
#include <cuda_bf16.h>
#include <math.h>
#include <string.h>

// Problem constants (fixed by the dataset)
#define EMB     512
#define HIDDEN  1024
#define HALF_H  512
#define BATCH   256
#define SEQLEN  512
#define NTOK    (BATCH * SEQLEN)   // 131072
#define KP      1536               // 3 * 512 packed-K for split-bf16 GEMMs

#define NCTA    128
#define NTHR    256
#define CLSZ    16                 // cluster size (one row group)

// ---------------------------------------------------------------------------
// Device globals (allocation-free scratch)
// ---------------------------------------------------------------------------
__device__ unsigned short g_a1p[(size_t)NTOK * KP];    // packed seq   [M][1536]
__device__ unsigned short g_hidp[(size_t)NTOK * KP];   // packed hid1  [M][1536]
__device__ unsigned short g_w1xp[HALF_H * KP];         // packed w1x   [512][1536] (n-major)
__device__ unsigned short g_w2xp[HIDDEN * KP];         // packed w2x   [1024][1536] (n-major)
__device__ unsigned short g_h_bf16[BATCH * HIDDEN];    // h (bf16)
__device__ unsigned short g_h1_bf16[BATCH * HALF_H];   // relu(h@W1h+b1h) (bf16)
__device__ volatile unsigned g_ggen[8 * 32];           // per-group barrier gen
__device__ unsigned g_gcnt[8 * 32];                    // per-group barrier count

// ---------------------------------------------------------------------------
// Helpers
// ---------------------------------------------------------------------------
static __device__ __forceinline__ unsigned smem_u32(const void* p) {
    unsigned a;
    asm("{ .reg .u64 t; cvta.to.shared.u64 t, %1; cvt.u32.u64 %0, t; }"
        : "=r"(a) : "l"(p));
    return a;
}

static __device__ __forceinline__ void ldsm_x4(unsigned& r0, unsigned& r1,
                                               unsigned& r2, unsigned& r3,
                                               unsigned addr) {
    asm volatile("ldmatrix.sync.aligned.m8n8.x4.shared.b16 {%0,%1,%2,%3}, [%4];"
                 : "=r"(r0), "=r"(r1), "=r"(r2), "=r"(r3) : "r"(addr));
}

static __device__ __forceinline__ void ldsm_x2(unsigned& r0, unsigned& r1,
                                               unsigned addr) {
    asm volatile("ldmatrix.sync.aligned.m8n8.x2.shared.b16 {%0,%1}, [%2];"
                 : "=r"(r0), "=r"(r1) : "r"(addr));
}

static __device__ __forceinline__ void mma_bf16(float& c0, float& c1, float& c2, float& c3,
                                                unsigned a0, unsigned a1, unsigned a2, unsigned a3,
                                                unsigned b0, unsigned b1) {
    asm volatile("mma.sync.aligned.m16n8k16.row.col.f32.bf16.bf16.f32 "
                 "{%0,%1,%2,%3}, {%4,%5,%6,%7}, {%8,%9}, {%0,%1,%2,%3};"
                 : "+f"(c0), "+f"(c1), "+f"(c2), "+f"(c3)
                 : "r"(a0), "r"(a1), "r"(a2), "r"(a3), "r"(b0), "r"(b1));
}

static __device__ __forceinline__ unsigned pack_bf16(float x, float y) {
    __nv_bfloat162 v = __floats2bfloat162_rn(x, y);
    unsigned u;
    memcpy(&u, &v, 4);
    return u;
}

static __device__ __forceinline__ unsigned short f2bf(float x) {
    __nv_bfloat16 v = __float2bfloat16(x);
    unsigned short u;
    memcpy(&u, &v, 2);
    return u;
}

static __device__ __forceinline__ float bf2f(unsigned short u) {
    __nv_bfloat16 v;
    memcpy(&v, &u, 2);
    return __bfloat162float(v);
}

static __device__ __forceinline__ void cp16(unsigned saddr, const void* gaddr) {
    asm volatile("cp.async.cg.shared.global [%0], [%1], 16;\n"
                 :: "r"(saddr), "l"(gaddr));
}
static __device__ __forceinline__ void cp_commit() {
    asm volatile("cp.async.commit_group;\n");
}
template <int N>
static __device__ __forceinline__ void cp_wait() {
    asm volatile("cp.async.wait_group %0;\n" :: "n"(N));
}

// Per-row-group software barrier (fallback path): 16 CTAs per group.
static __device__ __forceinline__ void groupbar(int g) {
    __threadfence();
    __syncthreads();
    if (threadIdx.x == 0) {
        const int gi = g * 32;
        unsigned gen = g_ggen[gi];
        if (atomicAdd(&g_gcnt[gi], 1) == 15) {
            g_gcnt[gi] = 0;
            __threadfence();
            g_ggen[gi] = gen + 1;
        } else {
            while (g_ggen[gi] == gen) { }
            __threadfence();
        }
    }
    __syncthreads();
}

// ---------------------------------------------------------------------------
// Packing kernels (hi/lo split, pairing baked into column order)
// ---------------------------------------------------------------------------
__global__ void pack_a_kernel(const float* __restrict__ A,
                              unsigned short* __restrict__ Ap)
{
    const size_t idx  = (size_t)blockIdx.x * blockDim.x + threadIdx.x;
    const size_t base = idx * 4;
    const size_t m    = base >> 9;
    const int    k    = (int)(base & 511);
    const float4 v = *(const float4*)(A + base);

    unsigned short h0 = f2bf(v.x), h1 = f2bf(v.y), h2 = f2bf(v.z), h3 = f2bf(v.w);
    unsigned short l0 = f2bf(v.x - bf2f(h0));
    unsigned short l1 = f2bf(v.y - bf2f(h1));
    unsigned short l2 = f2bf(v.z - bf2f(h2));
    unsigned short l3 = f2bf(v.w - bf2f(h3));

    uint2 hv, lv;
    hv.x = (unsigned)h0 | ((unsigned)h1 << 16);
    hv.y = (unsigned)h2 | ((unsigned)h3 << 16);
    lv.x = (unsigned)l0 | ((unsigned)l1 << 16);
    lv.y = (unsigned)l2 | ((unsigned)l3 << 16);

    unsigned short* row = Ap + m * KP;
    *(uint2*)(row + k)        = hv;
    *(uint2*)(row + 512 + k)  = lv;
    *(uint2*)(row + 1024 + k) = hv;
}

__global__ void pack_w_kernel(const float* __restrict__ W,
                              unsigned short* __restrict__ Wp, int N)
{
    const int idx = blockIdx.x * blockDim.x + threadIdx.x;
    if (idx >= N * 512) return;
    const int n = idx / 512;
    const int k = idx % 512;
    const float v = W[(size_t)k * N + n];
    unsigned short hi = f2bf(v);
    unsigned short lo = f2bf(v - bf2f(hi));
    unsigned short* row = Wp + (size_t)n * KP;
    row[k]        = hi;
    row[512 + k]  = hi;
    row[1024 + k] = lo;
}

// ---------------------------------------------------------------------------
// bf16 tensor-core GEMM, 4-stage cp.async pipeline, 64x64 warp tiles.
// BM=128, BN=128, BK=32, 128 threads, 4 warps (2m x 2n).
// LDSM/MMA ratio 0.25 (vs 0.375 before) -> less SMEM-crossbar bound.
// ---------------------------------------------------------------------------
#define TSTRIDE 40                             // halves per smem tile row
#define GSTAGES 4
#define GST_HALVES (128 * TSTRIDE)             // 5120
#define GST_BYTES  (GST_HALVES * 2)            // 10240
#define GSMEM_TOTAL (GSTAGES * GST_BYTES * 2)  // 81920

template <bool RELU, bool PACK>
__global__ __launch_bounds__(128, 2)
void bgemm_kernel(const unsigned short* __restrict__ Ap,
                  const unsigned short* __restrict__ Wp,
                  const float* __restrict__ bias,
                  float* __restrict__ Cf,
                  unsigned short* __restrict__ Cp,
                  int N)
{
    extern __shared__ char gsm[];
    unsigned short* As = (unsigned short*)gsm;
    unsigned short* Bs = (unsigned short*)(gsm + GSTAGES * GST_BYTES);

    const int tid  = threadIdx.x;
    const int m0   = blockIdx.y * 128;
    const int n0   = blockIdx.x * 128;
    const int wid  = tid >> 5;       // 0..3
    const int lane = tid & 31;
    const int wm   = wid & 1;        // m half
    const int wn   = wid >> 1;       // n half

    // loader: each thread owns one 128-row, stages 32 halves (64B = 4 cp16)
    const unsigned short* Ag = Ap + (size_t)(m0 + tid) * KP;
    const unsigned short* Bg = Wp + (size_t)(n0 + tid) * KP;

    const unsigned uA0 = smem_u32(As);
    const unsigned uB0 = smem_u32(Bs);
    const unsigned sa0 = uA0 + (unsigned)(tid * TSTRIDE) * 2;
    const unsigned sb0 = uB0 + (unsigned)(tid * TSTRIDE) * 2;

    const int aj  = lane >> 3;
    const int ar  = (aj & 1) * 8 + (lane & 7);
    const int akq = (aj >> 1) * 8;

    float acc[4][8][4];
#pragma unroll
    for (int i = 0; i < 4; i++)
#pragma unroll
        for (int j = 0; j < 8; j++)
#pragma unroll
            for (int q = 0; q < 4; q++) acc[i][j][q] = 0.0f;

#define G_ISSUE(it_) do {                                              \
        const int _buf = (it_) & (GSTAGES - 1);                        \
        const int _k0  = (it_) * 32;                                   \
        _Pragma("unroll")                                              \
        for (int _j = 0; _j < 4; _j++) {                               \
            cp16(sa0 + _buf * GST_BYTES + _j * 16, Ag + _k0 + _j * 8); \
            cp16(sb0 + _buf * GST_BYTES + _j * 16, Bg + _k0 + _j * 8); \
        }                                                              \
        cp_commit();                                                   \
    } while (0)

    G_ISSUE(0); G_ISSUE(1); G_ISSUE(2);

    const int NITER = KP / 32;   // 48
    for (int it = 0; it < NITER; it++) {
        if (it < NITER - 2)       cp_wait<2>();
        else if (it == NITER - 2) cp_wait<1>();
        else                      cp_wait<0>();
        __syncthreads();
        if (it + 3 < NITER) G_ISSUE(it + 3);

        const int buf = it & (GSTAGES - 1);
        const unsigned uA = uA0 + (unsigned)buf * GST_BYTES;
        const unsigned uB = uB0 + (unsigned)buf * GST_BYTES;

#pragma unroll
        for (int kk = 0; kk < 32; kk += 16) {
            unsigned a[4][4], b[4][4];
#pragma unroll
            for (int mi = 0; mi < 4; mi++)
                ldsm_x4(a[mi][0], a[mi][1], a[mi][2], a[mi][3],
                        uA + (unsigned)((wm * 64 + mi * 16 + ar) * TSTRIDE + kk + akq) * 2);
#pragma unroll
            for (int p = 0; p < 4; p++)
                ldsm_x4(b[p][0], b[p][1], b[p][2], b[p][3],
                        uB + (unsigned)((wn * 64 + p * 16 + ar) * TSTRIDE + kk + akq) * 2);
#pragma unroll
            for (int mi = 0; mi < 4; mi++) {
#pragma unroll
                for (int p = 0; p < 4; p++) {
                    mma_bf16(acc[mi][2*p][0], acc[mi][2*p][1], acc[mi][2*p][2], acc[mi][2*p][3],
                             a[mi][0], a[mi][1], a[mi][2], a[mi][3], b[p][0], b[p][2]);
                    mma_bf16(acc[mi][2*p+1][0], acc[mi][2*p+1][1], acc[mi][2*p+1][2], acc[mi][2*p+1][3],
                             a[mi][0], a[mi][1], a[mi][2], a[mi][3], b[p][1], b[p][3]);
                }
            }
        }
    }
#undef G_ISSUE

    // epilogue
    const int quad = lane >> 2;
    const int tq   = lane & 3;
#pragma unroll
    for (int mi = 0; mi < 4; mi++) {
#pragma unroll
        for (int ni = 0; ni < 8; ni++) {
            const int n = n0 + wn * 64 + ni * 8 + tq * 2;
            const float bb0 = bias[n], bb1 = bias[n + 1];
#pragma unroll
            for (int half = 0; half < 2; half++) {
                const int m = m0 + wm * 64 + mi * 16 + quad + half * 8;
                float v0 = acc[mi][ni][half * 2 + 0] + bb0;
                float v1 = acc[mi][ni][half * 2 + 1] + bb1;
                if (RELU) { v0 = fmaxf(v0, 0.f); v1 = fmaxf(v1, 0.f); }
                if (PACK) {
                    unsigned short h0 = f2bf(v0), h1 = f2bf(v1);
                    unsigned short l0 = f2bf(v0 - bf2f(h0));
                    unsigned short l1 = f2bf(v1 - bf2f(h1));
                    unsigned hv = (unsigned)h0 | ((unsigned)h1 << 16);
                    unsigned lv = (unsigned)l0 | ((unsigned)l1 << 16);
                    unsigned short* row = Cp + (size_t)m * KP;
                    *(unsigned*)(row + n)        = hv;
                    *(unsigned*)(row + 512 + n)  = lv;
                    *(unsigned*)(row + 1024 + n) = hv;
                } else {
                    float2 v; v.x = v0; v.y = v1;
                    *(float2*)(Cf + (size_t)m * N + n) = v;
                }
            }
        }
    }
}

// ---------------------------------------------------------------------------
// Persistent tensor-core recurrence kernel. Template: CL = use hardware
// cluster barriers (launched with 16-CTA clusters), else software groupbar.
// ---------------------------------------------------------------------------
#define WS1_STRIDE 1032
#define WS2_STRIDE 520
#define ACH_STRIDE 264
#define H1S_STRIDE 520
#define ACH_BUF    (32 * ACH_STRIDE)

#define OFF_WS1  0
#define OFF_WS2  (OFF_WS1 + 32 * WS1_STRIDE * 2)
#define OFF_ACH  (OFF_WS2 + 64 * WS2_STRIDE * 2)
#define OFF_H1S  (OFF_ACH + 3 * ACH_BUF * 2)
#define OFF_B1   (OFF_H1S + 32 * H1S_STRIDE * 2)
#define OFF_B2   (OFF_B1 + 32 * 4)
#define OFF_LEN  (OFF_B2 + 64 * 4)
#define SMEM_TOTAL (OFF_LEN + 32 * 4)

template <bool CL>
__global__ __launch_bounds__(NTHR, 1)
void recurrence_tc(const float* __restrict__ W1h,
                   const float* __restrict__ b1h,
                   const float* __restrict__ W2h,
                   const float* __restrict__ b2h,
                   const int*   __restrict__ lens,
                   float* __restrict__ out)
{
    extern __shared__ char smem[];
    unsigned short* ws1 = (unsigned short*)(smem + OFF_WS1);
    unsigned short* ws2 = (unsigned short*)(smem + OFF_WS2);
    unsigned short* h1s = (unsigned short*)(smem + OFF_H1S);
    float* b1s = (float*)(smem + OFF_B1);
    float* b2s = (float*)(smem + OFF_B2);
    int*   lns = (int*)(smem + OFF_LEN);

    const unsigned u_ws1 = smem_u32(ws1);
    const unsigned u_ws2 = smem_u32(ws2);
    const unsigned u_ach = smem_u32(smem + OFF_ACH);
    const unsigned u_h1s = smem_u32(h1s);

    const int tid  = threadIdx.x;
    const int cta  = blockIdx.x;
    const int wid  = tid >> 5;
    const int lane = tid & 31;
    const int quad = lane >> 2;
    const int tq   = lane & 3;

    const int grp = cta >> 4;
    const int mem = cta & 15;
    const int rA = grp * 32;
    const int cA = mem * 32;
    const int cB = mem * 64;

    const int mh = wid & 1;
    const int nb = wid >> 1;
    const int np = wid >> 1;

#define SYNCG() do {                                                       \
        if (CL) {                                                          \
            asm volatile("barrier.cluster.arrive.aligned;" ::: "memory");  \
            asm volatile("barrier.cluster.wait.aligned;"   ::: "memory");  \
        } else {                                                           \
            groupbar(grp);                                                 \
        }                                                                  \
    } while (0)

    for (int i = tid; i < 1024 * 32; i += NTHR) {
        int k = i >> 5, n = i & 31;
        ws1[n * WS1_STRIDE + k] = f2bf(W1h[(size_t)k * HALF_H + cA + n]);
    }
    for (int i = tid; i < 512 * 64; i += NTHR) {
        int k = i >> 6, n = i & 63;
        ws2[n * WS2_STRIDE + k] = f2bf(W2h[(size_t)k * HIDDEN + cB + n]);
    }
    if (tid < 32) { b1s[tid] = b1h[cA + tid]; lns[tid] = lens[rA + tid]; }
    if (tid < 64) b2s[tid] = b2h[cB + tid];

    {
        unsigned* hz = (unsigned*)(g_h_bf16 + (size_t)rA * HIDDEN);
        for (int i = tid; i < 1024; i += NTHR) hz[mem * 1024 + i] = 0u;
    }

    float hreg[2][4];
#pragma unroll
    for (int b = 0; b < 2; b++)
#pragma unroll
        for (int j = 0; j < 4; j++) hreg[b][j] = 0.0f;

    __syncthreads();
    SYNCG();

    const int aj   = lane >> 3;
    const int arow = mh * 16 + (aj & 1) * 8 + (lane & 7);
    const int akq  = (aj >> 1) * 8;
    const int li   = lane & 15;
    const int brow_in = li & 7;
    const int bkq  = (li >> 3) * 8;

#define ISSUE_A(ch_) do {                                                   \
        const int _buf = (ch_) % 3;                                         \
        const unsigned _dst = u_ach + (unsigned)_buf * (ACH_BUF * 2);       \
        const int _kb = (ch_) * 256;                                        \
        _Pragma("unroll")                                                   \
        for (int _j = 0; _j < 4; _j++) {                                    \
            int _lin = tid + _j * NTHR;                                     \
            int _row = _lin >> 5;                                           \
            int _cv  = (_lin & 31) * 8;                                     \
            cp16(_dst + (unsigned)(_row * ACH_STRIDE + _cv) * 2,            \
                 g_h_bf16 + (size_t)(rA + _row) * HIDDEN + _kb + _cv);      \
        }                                                                   \
        cp_commit();                                                        \
    } while (0)

    for (int t = 0; t < SEQLEN; t++) {
        // ================= PHASE A =================
        ISSUE_A(0); ISSUE_A(1);
        float ca[4] = {0.f, 0.f, 0.f, 0.f};
        for (int ch = 0; ch < 4; ch++) {
            if (ch < 3) cp_wait<1>(); else cp_wait<0>();
            __syncthreads();
            if (ch + 2 < 4) ISSUE_A(ch + 2);

            const unsigned uach = u_ach + (unsigned)(ch % 3) * (ACH_BUF * 2);
            const int kbase = ch * 256;
#pragma unroll 4
            for (int kk = 0; kk < 256; kk += 16) {
                unsigned a0, a1, a2, a3, b0, b1;
                ldsm_x4(a0, a1, a2, a3, uach + (unsigned)(arow * ACH_STRIDE + kk + akq) * 2);
                ldsm_x2(b0, b1, u_ws1 + (unsigned)((nb * 8 + brow_in) * WS1_STRIDE + kbase + kk + bkq) * 2);
                mma_bf16(ca[0], ca[1], ca[2], ca[3], a0, a1, a2, a3, b0, b1);
            }
        }
        {
            const int n = nb * 8 + tq * 2;
            const int m0w = mh * 16 + quad;
            float v0 = fmaxf(ca[0] + b1s[n], 0.f);
            float v1 = fmaxf(ca[1] + b1s[n + 1], 0.f);
            float v2 = fmaxf(ca[2] + b1s[n], 0.f);
            float v3 = fmaxf(ca[3] + b1s[n + 1], 0.f);
            __stcg((unsigned*)(g_h1_bf16 + (size_t)(rA + m0w) * HALF_H + cA + n), pack_bf16(v0, v1));
            __stcg((unsigned*)(g_h1_bf16 + (size_t)(rA + m0w + 8) * HALF_H + cA + n), pack_bf16(v2, v3));
        }
        SYNCG();

        // ================= PHASE B =================
#pragma unroll
        for (int j = 0; j < 8; j++) {
            int lin  = tid + j * NTHR;
            int row  = lin >> 6;
            int colv = (lin & 63) * 8;
            cp16(u_h1s + (unsigned)(row * H1S_STRIDE + colv) * 2,
                 g_h1_bf16 + (size_t)(rA + row) * HALF_H + colv);
        }
        cp_commit();
        cp_wait<0>();
        __syncthreads();

        float cb[2][4];
#pragma unroll
        for (int b = 0; b < 2; b++)
#pragma unroll
            for (int j = 0; j < 4; j++) cb[b][j] = 0.f;

#pragma unroll 4
        for (int kk = 0; kk < 512; kk += 16) {
            unsigned a0, a1, a2, a3;
            ldsm_x4(a0, a1, a2, a3, u_h1s + (unsigned)(arow * H1S_STRIDE + kk + akq) * 2);
#pragma unroll
            for (int b = 0; b < 2; b++) {
                unsigned b0, b1;
                ldsm_x2(b0, b1, u_ws2 + (unsigned)((np * 16 + b * 8 + brow_in) * WS2_STRIDE + kk + bkq) * 2);
                mma_bf16(cb[b][0], cb[b][1], cb[b][2], cb[b][3], a0, a1, a2, a3, b0, b1);
            }
        }

#pragma unroll
        for (int b = 0; b < 2; b++) {
            const int n = np * 16 + b * 8 + tq * 2;
            const float bb0 = b2s[n], bb1 = b2s[n + 1];
#pragma unroll
            for (int half = 0; half < 2; half++) {
                const int m = mh * 16 + quad + half * 8;
                const int bat = rA + m;
                const int col = cB + n;
                const size_t oidx = ((size_t)bat * SEQLEN + t) * HIDDEN + col;
                float xh0 = out[oidx], xh1 = out[oidx + 1];
                float nv0 = tanhf(xh0 + cb[b][half * 2 + 0] + bb0);
                float nv1 = tanhf(xh1 + cb[b][half * 2 + 1] + bb1);
                bool ok = t < lns[m];
                float h0 = ok ? nv0 : hreg[b][half * 2 + 0];
                float h1 = ok ? nv1 : hreg[b][half * 2 + 1];
                hreg[b][half * 2 + 0] = h0;
                hreg[b][half * 2 + 1] = h1;
                out[oidx]     = h0;
                out[oidx + 1] = h1;
                __stcg((unsigned*)(g_h_bf16 + (size_t)bat * HIDDEN + col), pack_bf16(h0, h1));
            }
        }
        SYNCG();
    }
#undef ISSUE_A
#undef SYNCG
}

// ---------------------------------------------------------------------------
extern "C" void kernel_launch(void* const* d_in, const int* in_sizes, int n_in,
                              void* d_out, int out_size)
{
    const float* seq  = (const float*)d_in[0];
    const int*   lens = (const int*)  d_in[1];
    const float* w1x  = (const float*)d_in[2];
    const float* b1x  = (const float*)d_in[3];
    const float* w2x  = (const float*)d_in[4];
    const float* b2x  = (const float*)d_in[5];
    const float* w1h  = (const float*)d_in[6];
    const float* b1h  = (const float*)d_in[7];
    const float* w2h  = (const float*)d_in[8];
    const float* b2h  = (const float*)d_in[9];
    float* out = (float*)d_out;

    unsigned short *a1p, *hidp, *w1xp, *w2xp;
    cudaGetSymbolAddress((void**)&a1p,  g_a1p);
    cudaGetSymbolAddress((void**)&hidp, g_hidp);
    cudaGetSymbolAddress((void**)&w1xp, g_w1xp);
    cudaGetSymbolAddress((void**)&w2xp, g_w2xp);

    static bool attr_set = false;
    if (!attr_set) {
        cudaFuncSetAttribute(recurrence_tc<false>,
                             cudaFuncAttributeMaxDynamicSharedMemorySize, SMEM_TOTAL);
        cudaFuncSetAttribute(recurrence_tc<true>,
                             cudaFuncAttributeMaxDynamicSharedMemorySize, SMEM_TOTAL);
        cudaFuncSetAttribute(recurrence_tc<true>,
                             cudaFuncAttributeNonPortableClusterSizeAllowed, 1);
        cudaFuncSetAttribute(bgemm_kernel<true, true>,
                             cudaFuncAttributeMaxDynamicSharedMemorySize, GSMEM_TOTAL);
        cudaFuncSetAttribute(bgemm_kernel<false, false>,
                             cudaFuncAttributeMaxDynamicSharedMemorySize, GSMEM_TOTAL);
        attr_set = true;
    }

    // Pack operands (hi/lo split)
    pack_a_kernel<<<(NTOK * EMB / 4) / 256, 256>>>(seq, a1p);
    pack_w_kernel<<<(HALF_H * 512 + 255) / 256, 256>>>(w1x, w1xp, HALF_H);
    pack_w_kernel<<<(HIDDEN * 512 + 255) / 256, 256>>>(w2x, w2xp, HIDDEN);

    // K1: hidp = pack(relu(seq @ w1x + b1x))
    bgemm_kernel<true, true><<<dim3(HALF_H / 128, NTOK / 128), 128, GSMEM_TOTAL>>>(
        a1p, w1xp, b1x, nullptr, hidp, HALF_H);

    // K2: out = hid @ w2x + b2x   (xh)
    bgemm_kernel<false, false><<<dim3(HIDDEN / 128, NTOK / 128), 128, GSMEM_TOTAL>>>(
        hidp, w2xp, b2x, out, nullptr, HIDDEN);

    // K3: recurrence — cluster path if 8x 16-CTA clusters fit, else fallback.
    {
        cudaLaunchConfig_t cfg = {};
        cfg.gridDim = dim3(NCTA, 1, 1);
        cfg.blockDim = dim3(NTHR, 1, 1);
        cfg.dynamicSmemBytes = SMEM_TOTAL;
        cudaLaunchAttribute attrs[1];
        attrs[0].id = cudaLaunchAttributeClusterDimension;
        attrs[0].val.clusterDim.x = CLSZ;
        attrs[0].val.clusterDim.y = 1;
        attrs[0].val.clusterDim.z = 1;
        cfg.attrs = attrs;
        cfg.numAttrs = 1;

        int nclusters = 0;
        cudaError_t qe = cudaOccupancyMaxActiveClusters(
            &nclusters, (void*)recurrence_tc<true>, &cfg);
        if (qe != cudaSuccess) { (void)cudaGetLastError(); nclusters = 0; }

        if (nclusters >= NCTA / CLSZ) {
            cudaLaunchKernelEx(&cfg, recurrence_tc<true>,
                               w1h, b1h, w2h, b2h, lens, out);
        } else {
            recurrence_tc<false><<<NCTA, NTHR, SMEM_TOTAL>>>(
                w1h, b1h, w2h, b2h, lens, out);
        }
    }
}

// round 8
// speedup vs baseline: 1.1542x; 1.1542x over previous
#include <cuda_runtime.h>
#include <cuda_bf16.h>
#include <math.h>
#include <string.h>

// Problem constants (fixed by the dataset)
#define EMB     512
#define HIDDEN  1024
#define HALF_H  512
#define BATCH   256
#define SEQLEN  512
#define NTOK    (BATCH * SEQLEN)   // 131072
#define KP      1536               // 3 * 512 packed-K for split-bf16 GEMMs

#define NCTA    128
#define NTHR    256

// ---------------------------------------------------------------------------
// Device globals (allocation-free scratch)
// ---------------------------------------------------------------------------
__device__ unsigned short g_a1p[(size_t)NTOK * KP];    // packed seq   [M][1536]
__device__ unsigned short g_hidp[(size_t)NTOK * KP];   // packed hid1  [M][1536]
__device__ unsigned short g_w1xp[HALF_H * KP];         // packed w1x   [512][1536] (n-major)
__device__ unsigned short g_w2xp[HIDDEN * KP];         // packed w2x   [1024][1536] (n-major)
__device__ unsigned short g_h_bf16[BATCH * HIDDEN];    // h (bf16), XOR-swizzled rows
__device__ unsigned short g_h1_bf16[BATCH * HALF_H];   // h1 (bf16), XOR-swizzled rows
__device__ volatile unsigned g_ggen[8 * 32];           // per-group barrier gen
__device__ unsigned g_gcnt[8 * 32];                    // per-group barrier count

// ---------------------------------------------------------------------------
// Helpers
// ---------------------------------------------------------------------------
static __device__ __forceinline__ unsigned smem_u32(const void* p) {
    unsigned a;
    asm("{ .reg .u64 t; cvta.to.shared.u64 t, %1; cvt.u32.u64 %0, t; }"
        : "=r"(a) : "l"(p));
    return a;
}

static __device__ __forceinline__ void ldsm_x4(unsigned& r0, unsigned& r1,
                                               unsigned& r2, unsigned& r3,
                                               unsigned addr) {
    asm volatile("ldmatrix.sync.aligned.m8n8.x4.shared.b16 {%0,%1,%2,%3}, [%4];"
                 : "=r"(r0), "=r"(r1), "=r"(r2), "=r"(r3) : "r"(addr));
}

static __device__ __forceinline__ void ldsm_x2(unsigned& r0, unsigned& r1,
                                               unsigned addr) {
    asm volatile("ldmatrix.sync.aligned.m8n8.x2.shared.b16 {%0,%1}, [%2];"
                 : "=r"(r0), "=r"(r1) : "r"(addr));
}

static __device__ __forceinline__ void mma_bf16(float& c0, float& c1, float& c2, float& c3,
                                                unsigned a0, unsigned a1, unsigned a2, unsigned a3,
                                                unsigned b0, unsigned b1) {
    asm volatile("mma.sync.aligned.m16n8k16.row.col.f32.bf16.bf16.f32 "
                 "{%0,%1,%2,%3}, {%4,%5,%6,%7}, {%8,%9}, {%0,%1,%2,%3};"
                 : "+f"(c0), "+f"(c1), "+f"(c2), "+f"(c3)
                 : "r"(a0), "r"(a1), "r"(a2), "r"(a3), "r"(b0), "r"(b1));
}

static __device__ __forceinline__ unsigned pack_bf16(float x, float y) {
    __nv_bfloat162 v = __floats2bfloat162_rn(x, y);
    unsigned u;
    memcpy(&u, &v, 4);
    return u;
}

static __device__ __forceinline__ unsigned short f2bf(float x) {
    __nv_bfloat16 v = __float2bfloat16(x);
    unsigned short u;
    memcpy(&u, &v, 2);
    return u;
}

static __device__ __forceinline__ float bf2f(unsigned short u) {
    __nv_bfloat16 v;
    memcpy(&v, &u, 2);
    return __bfloat162float(v);
}

static __device__ __forceinline__ void cp16(unsigned saddr, const void* gaddr) {
    asm volatile("cp.async.cg.shared.global [%0], [%1], 16;\n"
                 :: "r"(saddr), "l"(gaddr));
}
static __device__ __forceinline__ void cp_commit() {
    asm volatile("cp.async.commit_group;\n");
}
template <int N>
static __device__ __forceinline__ void cp_wait() {
    asm volatile("cp.async.wait_group %0;\n" :: "n"(N));
}

// ---- mbarrier + 1D bulk-copy (UBLKCP) helpers ----
static __device__ __forceinline__ void mbar_init(unsigned bar) {
    asm volatile("mbarrier.init.shared.b64 [%0], 1;" :: "r"(bar) : "memory");
}
static __device__ __forceinline__ void mbar_expect(unsigned bar, unsigned bytes) {
    asm volatile("mbarrier.arrive.expect_tx.shared.b64 _, [%0], %1;"
                 :: "r"(bar), "r"(bytes) : "memory");
}
static __device__ __forceinline__ void bulk_g2s(unsigned dst, const void* src,
                                                unsigned bytes, unsigned bar) {
    asm volatile("cp.async.bulk.shared::cta.global.mbarrier::complete_tx::bytes "
                 "[%0], [%1], %2, [%3];"
                 :: "r"(dst), "l"(src), "r"(bytes), "r"(bar) : "memory");
}
static __device__ __forceinline__ void mbar_wait(unsigned bar, unsigned parity) {
    asm volatile("{\n\t"
                 ".reg .pred p;\n\t"
                 "WAIT_%=:\n\t"
                 "mbarrier.try_wait.parity.shared::cta.b64 p, [%0], %1;\n\t"
                 "@!p bra WAIT_%=;\n\t"
                 "}"
                 :: "r"(bar), "r"(parity) : "memory");
}

// Per-row-group software barrier: 16 CTAs per group.
static __device__ __forceinline__ void groupbar(int g) {
    __threadfence();
    __syncthreads();
    if (threadIdx.x == 0) {
        const int gi = g * 32;
        unsigned gen = g_ggen[gi];
        if (atomicAdd(&g_gcnt[gi], 1) == 15) {
            g_gcnt[gi] = 0;
            __threadfence();
            g_ggen[gi] = gen + 1;
        } else {
            while (g_ggen[gi] == gen) { }
            __threadfence();
        }
    }
    __syncthreads();
}

// ---------------------------------------------------------------------------
// Packing kernels (hi/lo split, pairing baked into column order)
// ---------------------------------------------------------------------------
__global__ void pack_a_kernel(const float* __restrict__ A,
                              unsigned short* __restrict__ Ap)
{
    const size_t idx  = (size_t)blockIdx.x * blockDim.x + threadIdx.x;
    const size_t base = idx * 4;
    const size_t m    = base >> 9;
    const int    k    = (int)(base & 511);
    const float4 v = *(const float4*)(A + base);

    unsigned short h0 = f2bf(v.x), h1 = f2bf(v.y), h2 = f2bf(v.z), h3 = f2bf(v.w);
    unsigned short l0 = f2bf(v.x - bf2f(h0));
    unsigned short l1 = f2bf(v.y - bf2f(h1));
    unsigned short l2 = f2bf(v.z - bf2f(h2));
    unsigned short l3 = f2bf(v.w - bf2f(h3));

    uint2 hv, lv;
    hv.x = (unsigned)h0 | ((unsigned)h1 << 16);
    hv.y = (unsigned)h2 | ((unsigned)h3 << 16);
    lv.x = (unsigned)l0 | ((unsigned)l1 << 16);
    lv.y = (unsigned)l2 | ((unsigned)l3 << 16);

    unsigned short* row = Ap + m * KP;
    *(uint2*)(row + k)        = hv;
    *(uint2*)(row + 512 + k)  = lv;
    *(uint2*)(row + 1024 + k) = hv;
}

__global__ void pack_w_kernel(const float* __restrict__ W,
                              unsigned short* __restrict__ Wp, int N)
{
    const int idx = blockIdx.x * blockDim.x + threadIdx.x;
    if (idx >= N * 512) return;
    const int n = idx / 512;
    const int k = idx % 512;
    const float v = W[(size_t)k * N + n];
    unsigned short hi = f2bf(v);
    unsigned short lo = f2bf(v - bf2f(hi));
    unsigned short* row = Wp + (size_t)n * KP;
    row[k]        = hi;
    row[512 + k]  = hi;
    row[1024 + k] = lo;
}

// ---------------------------------------------------------------------------
// bf16 tensor-core GEMM (round-4 proven version): 4-stage cp.async pipeline,
// BM=128, BN=128, BK=32, 256 threads, 8 warps (2m x 4n), warp tile 64x32.
// ---------------------------------------------------------------------------
#define TSTRIDE 40
#define GSTAGES 4
#define GST_HALVES (128 * TSTRIDE)
#define GST_BYTES  (GST_HALVES * 2)
#define GSMEM_TOTAL (GSTAGES * GST_BYTES * 2)

template <bool RELU, bool PACK>
__global__ __launch_bounds__(256, 2)
void bgemm_kernel(const unsigned short* __restrict__ Ap,
                  const unsigned short* __restrict__ Wp,
                  const float* __restrict__ bias,
                  float* __restrict__ Cf,
                  unsigned short* __restrict__ Cp,
                  int N)
{
    extern __shared__ char gsm[];
    unsigned short* As = (unsigned short*)gsm;
    unsigned short* Bs = (unsigned short*)(gsm + GSTAGES * GST_BYTES);

    const int tid  = threadIdx.x;
    const int m0   = blockIdx.y * 128;
    const int n0   = blockIdx.x * 128;
    const int wid  = tid >> 5;
    const int lane = tid & 31;
    const int wm   = wid & 1;
    const int wn   = wid >> 1;

    const int lrow = tid >> 1;
    const int lcol = (tid & 1) * 16;
    const unsigned short* Ag = Ap + (size_t)(m0 + lrow) * KP + lcol;
    const unsigned short* Bg = Wp + (size_t)(n0 + lrow) * KP + lcol;

    const unsigned uA0 = smem_u32(As);
    const unsigned uB0 = smem_u32(Bs);
    const unsigned sa0 = uA0 + (unsigned)(lrow * TSTRIDE + lcol) * 2;
    const unsigned sb0 = uB0 + (unsigned)(lrow * TSTRIDE + lcol) * 2;

    const int aj  = lane >> 3;
    const int ar  = (aj & 1) * 8 + (lane & 7);
    const int akq = (aj >> 1) * 8;

    float acc[4][4][4];
#pragma unroll
    for (int i = 0; i < 4; i++)
#pragma unroll
        for (int j = 0; j < 4; j++)
#pragma unroll
            for (int q = 0; q < 4; q++) acc[i][j][q] = 0.0f;

#define G_ISSUE(it_) do {                                              \
        const int _buf = (it_) & (GSTAGES - 1);                        \
        const int _k0  = (it_) * 32;                                   \
        cp16(sa0 + _buf * GST_BYTES,      Ag + _k0);                   \
        cp16(sa0 + _buf * GST_BYTES + 16, Ag + _k0 + 8);               \
        cp16(sb0 + _buf * GST_BYTES,      Bg + _k0);                   \
        cp16(sb0 + _buf * GST_BYTES + 16, Bg + _k0 + 8);               \
        cp_commit();                                                   \
    } while (0)

    G_ISSUE(0); G_ISSUE(1); G_ISSUE(2);

    const int NITER = KP / 32;   // 48
    for (int it = 0; it < NITER; it++) {
        if (it < NITER - 2)       cp_wait<2>();
        else if (it == NITER - 2) cp_wait<1>();
        else                      cp_wait<0>();
        __syncthreads();
        if (it + 3 < NITER) G_ISSUE(it + 3);

        const int buf = it & (GSTAGES - 1);
        const unsigned uA = uA0 + (unsigned)buf * GST_BYTES;
        const unsigned uB = uB0 + (unsigned)buf * GST_BYTES;

#pragma unroll
        for (int kk = 0; kk < 32; kk += 16) {
            unsigned a[4][4], b[2][4];
#pragma unroll
            for (int mi = 0; mi < 4; mi++)
                ldsm_x4(a[mi][0], a[mi][1], a[mi][2], a[mi][3],
                        uA + (unsigned)((wm * 64 + mi * 16 + ar) * TSTRIDE + kk + akq) * 2);
#pragma unroll
            for (int p = 0; p < 2; p++)
                ldsm_x4(b[p][0], b[p][1], b[p][2], b[p][3],
                        uB + (unsigned)((wn * 32 + p * 16 + ar) * TSTRIDE + kk + akq) * 2);
#pragma unroll
            for (int mi = 0; mi < 4; mi++) {
#pragma unroll
                for (int p = 0; p < 2; p++) {
                    mma_bf16(acc[mi][2*p][0], acc[mi][2*p][1], acc[mi][2*p][2], acc[mi][2*p][3],
                             a[mi][0], a[mi][1], a[mi][2], a[mi][3], b[p][0], b[p][2]);
                    mma_bf16(acc[mi][2*p+1][0], acc[mi][2*p+1][1], acc[mi][2*p+1][2], acc[mi][2*p+1][3],
                             a[mi][0], a[mi][1], a[mi][2], a[mi][3], b[p][1], b[p][3]);
                }
            }
        }
    }
#undef G_ISSUE

    const int quad = lane >> 2;
    const int tq   = lane & 3;
#pragma unroll
    for (int mi = 0; mi < 4; mi++) {
#pragma unroll
        for (int ni = 0; ni < 4; ni++) {
            const int n = n0 + wn * 32 + ni * 8 + tq * 2;
            const float bb0 = bias[n], bb1 = bias[n + 1];
#pragma unroll
            for (int half = 0; half < 2; half++) {
                const int m = m0 + wm * 64 + mi * 16 + quad + half * 8;
                float v0 = acc[mi][ni][half * 2 + 0] + bb0;
                float v1 = acc[mi][ni][half * 2 + 1] + bb1;
                if (RELU) { v0 = fmaxf(v0, 0.f); v1 = fmaxf(v1, 0.f); }
                if (PACK) {
                    unsigned short h0 = f2bf(v0), h1 = f2bf(v1);
                    unsigned short l0 = f2bf(v0 - bf2f(h0));
                    unsigned short l1 = f2bf(v1 - bf2f(h1));
                    unsigned hv = (unsigned)h0 | ((unsigned)h1 << 16);
                    unsigned lv = (unsigned)l0 | ((unsigned)l1 << 16);
                    unsigned short* row = Cp + (size_t)m * KP;
                    *(unsigned*)(row + n)        = hv;
                    *(unsigned*)(row + 512 + n)  = lv;
                    *(unsigned*)(row + 1024 + n) = hv;
                } else {
                    float2 v; v.x = v0; v.y = v1;
                    *(float2*)(Cf + (size_t)m * N + n) = v;
                }
            }
        }
    }
}

// ---------------------------------------------------------------------------
// Persistent tensor-core recurrence kernel.
// h / h1 exchanged through global in an XOR-swizzled row layout; staged into
// SMEM with single cp.async.bulk copies (UBLKCP) per m-half, mbarrier-timed.
// Swizzle: 16B unit u of row r is stored at u ^ (r & 7)  (row strides are
// multiples of 128B, so linear bulk copy -> conflict-free ldmatrix).
// ---------------------------------------------------------------------------
#define WS1_STRIDE 1032
#define WS2_STRIDE 520

#define OFF_WS1  0                                   // 66048
#define OFF_WS2  (OFF_WS1 + 32 * WS1_STRIDE * 2)     // 66048
#define OFF_ACH  (OFF_WS2 + 64 * WS2_STRIDE * 2)     // 132608 (128B aligned)
#define OFF_H1S  (OFF_ACH + 65536)                   // 198144
#define OFF_B1   (OFF_H1S + 32768)                   // 230912
#define OFF_B2   (OFF_B1 + 32 * 4)                   // 231040
#define OFF_LEN  (OFF_B2 + 64 * 4)                   // 231296
#define OFF_MBAR (OFF_LEN + 32 * 4)                  // 231424
#define SMEM_TOTAL (OFF_MBAR + 4 * 8)                // 231456

__global__ __launch_bounds__(NTHR, 1)
void recurrence_tc(const float* __restrict__ W1h,
                   const float* __restrict__ b1h,
                   const float* __restrict__ W2h,
                   const float* __restrict__ b2h,
                   const int*   __restrict__ lens,
                   float* __restrict__ out)
{
    extern __shared__ char smem[];
    unsigned short* ws1 = (unsigned short*)(smem + OFF_WS1);
    unsigned short* ws2 = (unsigned short*)(smem + OFF_WS2);
    float* b1s = (float*)(smem + OFF_B1);
    float* b2s = (float*)(smem + OFF_B2);
    int*   lns = (int*)(smem + OFF_LEN);

    const unsigned u_ws1 = smem_u32(ws1);
    const unsigned u_ws2 = smem_u32(ws2);
    const unsigned u_ach = smem_u32(smem + OFF_ACH);
    const unsigned u_h1s = smem_u32(smem + OFF_H1S);
    const unsigned u_bar = smem_u32(smem + OFF_MBAR);   // barA0 barA1 barB0 barB1

    const int tid  = threadIdx.x;
    const int cta  = blockIdx.x;
    const int wid  = tid >> 5;
    const int lane = tid & 31;
    const int quad = lane >> 2;
    const int tq   = lane & 3;

    const int grp = cta >> 4;
    const int mem = cta & 15;
    const int rA = grp * 32;
    const int cA = mem * 32;
    const int cB = mem * 64;

    const int mh = wid & 1;
    const int nb = wid >> 1;
    const int np = wid >> 1;

    // init weights/bias/lens in SMEM
    for (int i = tid; i < 1024 * 32; i += NTHR) {
        int k = i >> 5, n = i & 31;
        ws1[n * WS1_STRIDE + k] = f2bf(W1h[(size_t)k * HALF_H + cA + n]);
    }
    for (int i = tid; i < 512 * 64; i += NTHR) {
        int k = i >> 6, n = i & 63;
        ws2[n * WS2_STRIDE + k] = f2bf(W2h[(size_t)k * HIDDEN + cB + n]);
    }
    if (tid < 32) { b1s[tid] = b1h[cA + tid]; lns[tid] = lens[rA + tid]; }
    if (tid < 64) b2s[tid] = b2h[cB + tid];

    if (tid == 0) {
        mbar_init(u_bar + 0);
        mbar_init(u_bar + 8);
        mbar_init(u_bar + 16);
        mbar_init(u_bar + 24);
    }

    // zero this group's h slab (zeros are swizzle-invariant)
    {
        unsigned* hz = (unsigned*)(g_h_bf16 + (size_t)rA * HIDDEN);
        for (int i = tid; i < 1024; i += NTHR) hz[mem * 1024 + i] = 0u;
    }

    float hreg[2][4];
#pragma unroll
    for (int b = 0; b < 2; b++)
#pragma unroll
        for (int j = 0; j < 4; j++) hreg[b][j] = 0.0f;

    groupbar(grp);   // includes __syncthreads: mbarriers + zeros visible

    // ldmatrix lane mapping
    const int aj   = lane >> 3;
    const int arow = mh * 16 + (aj & 1) * 8 + (lane & 7);
    const int ku   = aj >> 1;                 // k-unit sub-offset (0/1)
    const int swz  = arow & 7;                // row swizzle
    const unsigned baseA = u_ach + (unsigned)arow * 2048;   // h rows: 2KB
    const unsigned baseB = u_h1s + (unsigned)arow * 1024;   // h1 rows: 1KB
    const int li   = lane & 15;
    const int brow_in = li & 7;
    const int bkq  = (li >> 3) * 8;

    const unsigned barA = u_bar + (unsigned)mh * 8;
    const unsigned barB = u_bar + 16 + (unsigned)mh * 8;

    for (int t = 0; t < SEQLEN; t++) {
        const unsigned par = (unsigned)(t & 1);

        // ================= PHASE A: h1 = relu(h @ W1h + b1) =================
        if (tid == 0) {
            mbar_expect(u_bar + 0, 32768);
            bulk_g2s(u_ach, g_h_bf16 + (size_t)rA * HIDDEN, 32768, u_bar + 0);
            mbar_expect(u_bar + 8, 32768);
            bulk_g2s(u_ach + 32768, g_h_bf16 + (size_t)(rA + 16) * HIDDEN, 32768, u_bar + 8);
        }
        mbar_wait(barA, par);

        float ca[4] = {0.f, 0.f, 0.f, 0.f};
#pragma unroll 8
        for (int kk = 0; kk < 1024; kk += 16) {
            unsigned a0, a1, a2, a3, b0, b1;
            ldsm_x4(a0, a1, a2, a3,
                    baseA + (unsigned)((((kk >> 3) + ku) ^ swz) << 4));
            ldsm_x2(b0, b1, u_ws1 + (unsigned)((nb * 8 + brow_in) * WS1_STRIDE + kk + bkq) * 2);
            mma_bf16(ca[0], ca[1], ca[2], ca[3], a0, a1, a2, a3, b0, b1);
        }
        {
            const int n = nb * 8 + tq * 2;
            const int u = (cA >> 3) + nb;            // 16B unit of col
            const int m0w = mh * 16 + quad;
            const int bat0 = rA + m0w;
            const int bat1 = bat0 + 8;
            float v0 = fmaxf(ca[0] + b1s[n], 0.f);
            float v1 = fmaxf(ca[1] + b1s[n + 1], 0.f);
            float v2 = fmaxf(ca[2] + b1s[n], 0.f);
            float v3 = fmaxf(ca[3] + b1s[n + 1], 0.f);
            __stcg((unsigned*)(g_h1_bf16 + (size_t)bat0 * HALF_H
                               + ((u ^ (bat0 & 7)) << 3) + tq * 2), pack_bf16(v0, v1));
            __stcg((unsigned*)(g_h1_bf16 + (size_t)bat1 * HALF_H
                               + ((u ^ (bat1 & 7)) << 3) + tq * 2), pack_bf16(v2, v3));
        }
        groupbar(grp);

        // ================= PHASE B: h = tanh(xh + h1 @ W2h + b2) ============
        if (tid == 0) {
            mbar_expect(u_bar + 16, 16384);
            bulk_g2s(u_h1s, g_h1_bf16 + (size_t)rA * HALF_H, 16384, u_bar + 16);
            mbar_expect(u_bar + 24, 16384);
            bulk_g2s(u_h1s + 16384, g_h1_bf16 + (size_t)(rA + 16) * HALF_H, 16384, u_bar + 24);
        }
        mbar_wait(barB, par);

        float cb[2][4];
#pragma unroll
        for (int b = 0; b < 2; b++)
#pragma unroll
            for (int j = 0; j < 4; j++) cb[b][j] = 0.f;

#pragma unroll 8
        for (int kk = 0; kk < 512; kk += 16) {
            unsigned a0, a1, a2, a3;
            ldsm_x4(a0, a1, a2, a3,
                    baseB + (unsigned)((((kk >> 3) + ku) ^ swz) << 4));
#pragma unroll
            for (int b = 0; b < 2; b++) {
                unsigned b0, b1;
                ldsm_x2(b0, b1, u_ws2 + (unsigned)((np * 16 + b * 8 + brow_in) * WS2_STRIDE + kk + bkq) * 2);
                mma_bf16(cb[b][0], cb[b][1], cb[b][2], cb[b][3], a0, a1, a2, a3, b0, b1);
            }
        }

#pragma unroll
        for (int b = 0; b < 2; b++) {
            const int n = np * 16 + b * 8 + tq * 2;
            const int u = (cB >> 3) + np * 2 + b;
            const float bb0 = b2s[n], bb1 = b2s[n + 1];
#pragma unroll
            for (int half = 0; half < 2; half++) {
                const int m = mh * 16 + quad + half * 8;
                const int bat = rA + m;
                const int col = cB + n;
                const size_t oidx = ((size_t)bat * SEQLEN + t) * HIDDEN + col;
                float2 xh = *(const float2*)(out + oidx);
                float nv0 = tanhf(xh.x + cb[b][half * 2 + 0] + bb0);
                float nv1 = tanhf(xh.y + cb[b][half * 2 + 1] + bb1);
                bool ok = t < lns[m];
                float h0 = ok ? nv0 : hreg[b][half * 2 + 0];
                float h1 = ok ? nv1 : hreg[b][half * 2 + 1];
                hreg[b][half * 2 + 0] = h0;
                hreg[b][half * 2 + 1] = h1;
                float2 hv; hv.x = h0; hv.y = h1;
                *(float2*)(out + oidx) = hv;
                __stcg((unsigned*)(g_h_bf16 + (size_t)bat * HIDDEN
                                   + ((u ^ (bat & 7)) << 3) + tq * 2), pack_bf16(h0, h1));
            }
        }
        groupbar(grp);
    }
}

// ---------------------------------------------------------------------------
extern "C" void kernel_launch(void* const* d_in, const int* in_sizes, int n_in,
                              void* d_out, int out_size)
{
    const float* seq  = (const float*)d_in[0];
    const int*   lens = (const int*)  d_in[1];
    const float* w1x  = (const float*)d_in[2];
    const float* b1x  = (const float*)d_in[3];
    const float* w2x  = (const float*)d_in[4];
    const float* b2x  = (const float*)d_in[5];
    const float* w1h  = (const float*)d_in[6];
    const float* b1h  = (const float*)d_in[7];
    const float* w2h  = (const float*)d_in[8];
    const float* b2h  = (const float*)d_in[9];
    float* out = (float*)d_out;

    unsigned short *a1p, *hidp, *w1xp, *w2xp;
    cudaGetSymbolAddress((void**)&a1p,  g_a1p);
    cudaGetSymbolAddress((void**)&hidp, g_hidp);
    cudaGetSymbolAddress((void**)&w1xp, g_w1xp);
    cudaGetSymbolAddress((void**)&w2xp, g_w2xp);

    static bool attr_set = false;
    if (!attr_set) {
        cudaFuncSetAttribute(recurrence_tc,
                             cudaFuncAttributeMaxDynamicSharedMemorySize, SMEM_TOTAL);
        cudaFuncSetAttribute(bgemm_kernel<true, true>,
                             cudaFuncAttributeMaxDynamicSharedMemorySize, GSMEM_TOTAL);
        cudaFuncSetAttribute(bgemm_kernel<false, false>,
                             cudaFuncAttributeMaxDynamicSharedMemorySize, GSMEM_TOTAL);
        attr_set = true;
    }

    // Pack operands (hi/lo split)
    pack_a_kernel<<<(NTOK * EMB / 4) / 256, 256>>>(seq, a1p);
    pack_w_kernel<<<(HALF_H * 512 + 255) / 256, 256>>>(w1x, w1xp, HALF_H);
    pack_w_kernel<<<(HIDDEN * 512 + 255) / 256, 256>>>(w2x, w2xp, HIDDEN);

    // K1: hidp = pack(relu(seq @ w1x + b1x))
    bgemm_kernel<true, true><<<dim3(HALF_H / 128, NTOK / 128), 256, GSMEM_TOTAL>>>(
        a1p, w1xp, b1x, nullptr, hidp, HALF_H);

    // K2: out = hid @ w2x + b2x   (xh)
    bgemm_kernel<false, false><<<dim3(HIDDEN / 128, NTOK / 128), 256, GSMEM_TOTAL>>>(
        hidp, w2xp, b2x, out, nullptr, HIDDEN);

    // K3: persistent tensor-core recurrence (bulk-copy staging)
    recurrence_tc<<<NCTA, NTHR, SMEM_TOTAL>>>(w1h, b1h, w2h, b2h, lens, out);
}

// round 10
// speedup vs baseline: 1.3641x; 1.1819x over previous
#include <cuda_runtime.h>
#include <cuda_bf16.h>
#include <math.h>
#include <string.h>

// Problem constants (fixed by the dataset)
#define EMB     512
#define HIDDEN  1024
#define HALF_H  512
#define BATCH   256
#define SEQLEN  512
#define NTOK    (BATCH * SEQLEN)   // 131072
#define KP      1536               // 3 * 512 packed-K for split-bf16 GEMMs

#define NCTA    128
#define NTHR    256

// ---------------------------------------------------------------------------
// Device globals (allocation-free scratch)
// h / h1 exchange buffers are chunk-contiguous per producer CTA:
//   g_h_bf16 : [8 groups][16 producers][32 rows][64 cols]  (rows XOR-swizzled)
//   g_h1_bf16: [8 groups][16 producers][32 rows][32 cols]  (rows XOR-swizzled)
// ---------------------------------------------------------------------------
__device__ unsigned short g_a1p[(size_t)NTOK * KP];    // packed seq   [M][1536]
__device__ unsigned short g_hidp[(size_t)NTOK * KP];   // packed hid1  [M][1536]
__device__ unsigned short g_w1xp[HALF_H * KP];         // packed w1x   [512][1536] (n-major)
__device__ unsigned short g_w2xp[HIDDEN * KP];         // packed w2x   [1024][1536] (n-major)
__device__ unsigned short g_h_bf16[BATCH * HIDDEN];
__device__ unsigned short g_h1_bf16[BATCH * HALF_H];
__device__ volatile unsigned g_ggen[8 * 32];           // init barrier gen
__device__ unsigned g_gcnt[8 * 32];                    // init barrier count
__device__ volatile unsigned g_hflag[8][16 * 32];      // h ready flags (128B apart)
__device__ volatile unsigned g_h1flag[8][16 * 32];     // h1 ready flags

// ---------------------------------------------------------------------------
// Helpers
// ---------------------------------------------------------------------------
static __device__ __forceinline__ unsigned smem_u32(const void* p) {
    unsigned a;
    asm("{ .reg .u64 t; cvta.to.shared.u64 t, %1; cvt.u32.u64 %0, t; }"
        : "=r"(a) : "l"(p));
    return a;
}

static __device__ __forceinline__ void ldsm_x4(unsigned& r0, unsigned& r1,
                                               unsigned& r2, unsigned& r3,
                                               unsigned addr) {
    asm volatile("ldmatrix.sync.aligned.m8n8.x4.shared.b16 {%0,%1,%2,%3}, [%4];"
                 : "=r"(r0), "=r"(r1), "=r"(r2), "=r"(r3) : "r"(addr));
}

static __device__ __forceinline__ void ldsm_x2(unsigned& r0, unsigned& r1,
                                               unsigned addr) {
    asm volatile("ldmatrix.sync.aligned.m8n8.x2.shared.b16 {%0,%1}, [%2];"
                 : "=r"(r0), "=r"(r1) : "r"(addr));
}

static __device__ __forceinline__ void mma_bf16(float& c0, float& c1, float& c2, float& c3,
                                                unsigned a0, unsigned a1, unsigned a2, unsigned a3,
                                                unsigned b0, unsigned b1) {
    asm volatile("mma.sync.aligned.m16n8k16.row.col.f32.bf16.bf16.f32 "
                 "{%0,%1,%2,%3}, {%4,%5,%6,%7}, {%8,%9}, {%0,%1,%2,%3};"
                 : "+f"(c0), "+f"(c1), "+f"(c2), "+f"(c3)
                 : "r"(a0), "r"(a1), "r"(a2), "r"(a3), "r"(b0), "r"(b1));
}

static __device__ __forceinline__ unsigned pack_bf16(float x, float y) {
    __nv_bfloat162 v = __floats2bfloat162_rn(x, y);
    unsigned u;
    memcpy(&u, &v, 4);
    return u;
}

static __device__ __forceinline__ unsigned short f2bf(float x) {
    __nv_bfloat16 v = __float2bfloat16(x);
    unsigned short u;
    memcpy(&u, &v, 2);
    return u;
}

static __device__ __forceinline__ float bf2f(unsigned short u) {
    __nv_bfloat16 v;
    memcpy(&v, &u, 2);
    return __bfloat162float(v);
}

static __device__ __forceinline__ void cp16(unsigned saddr, const void* gaddr) {
    asm volatile("cp.async.cg.shared.global [%0], [%1], 16;\n"
                 :: "r"(saddr), "l"(gaddr));
}
static __device__ __forceinline__ void cp_commit() {
    asm volatile("cp.async.commit_group;\n");
}
template <int N>
static __device__ __forceinline__ void cp_wait() {
    asm volatile("cp.async.wait_group %0;\n" :: "n"(N));
}

// ---- mbarrier + 1D bulk-copy helpers ----
static __device__ __forceinline__ void mbar_init(unsigned bar, unsigned count) {
    asm volatile("mbarrier.init.shared.b64 [%0], %1;" :: "r"(bar), "r"(count) : "memory");
}
static __device__ __forceinline__ void mbar_expect(unsigned bar, unsigned bytes) {
    asm volatile("mbarrier.arrive.expect_tx.shared.b64 _, [%0], %1;"
                 :: "r"(bar), "r"(bytes) : "memory");
}
static __device__ __forceinline__ void bulk_g2s(unsigned dst, const void* src,
                                                unsigned bytes, unsigned bar) {
    asm volatile("cp.async.bulk.shared::cta.global.mbarrier::complete_tx::bytes "
                 "[%0], [%1], %2, [%3];"
                 :: "r"(dst), "l"(src), "r"(bytes), "r"(bar) : "memory");
}
static __device__ __forceinline__ void mbar_wait(unsigned bar, unsigned parity) {
    asm volatile("{\n\t"
                 ".reg .pred p;\n\t"
                 "WAIT_%=:\n\t"
                 "mbarrier.try_wait.parity.shared::cta.b64 p, [%0], %1;\n\t"
                 "@!p bra WAIT_%=;\n\t"
                 "}"
                 :: "r"(bar), "r"(parity) : "memory");
}

// Init-time software barrier (atomic, self-resetting across replays).
static __device__ __forceinline__ void groupbar(int g) {
    __threadfence();
    __syncthreads();
    if (threadIdx.x == 0) {
        const int gi = g * 32;
        unsigned gen = g_ggen[gi];
        if (atomicAdd(&g_gcnt[gi], 1) == 15) {
            g_gcnt[gi] = 0;
            __threadfence();
            g_ggen[gi] = gen + 1;
        } else {
            while (g_ggen[gi] == gen) { }
            __threadfence();
        }
    }
    __syncthreads();
}

// ---------------------------------------------------------------------------
// Packing kernels (hi/lo split, pairing baked into column order)
// ---------------------------------------------------------------------------
__global__ void pack_a_kernel(const float* __restrict__ A,
                              unsigned short* __restrict__ Ap)
{
    const size_t idx  = (size_t)blockIdx.x * blockDim.x + threadIdx.x;
    const size_t base = idx * 4;
    const size_t m    = base >> 9;
    const int    k    = (int)(base & 511);
    const float4 v = *(const float4*)(A + base);

    unsigned short h0 = f2bf(v.x), h1 = f2bf(v.y), h2 = f2bf(v.z), h3 = f2bf(v.w);
    unsigned short l0 = f2bf(v.x - bf2f(h0));
    unsigned short l1 = f2bf(v.y - bf2f(h1));
    unsigned short l2 = f2bf(v.z - bf2f(h2));
    unsigned short l3 = f2bf(v.w - bf2f(h3));

    uint2 hv, lv;
    hv.x = (unsigned)h0 | ((unsigned)h1 << 16);
    hv.y = (unsigned)h2 | ((unsigned)h3 << 16);
    lv.x = (unsigned)l0 | ((unsigned)l1 << 16);
    lv.y = (unsigned)l2 | ((unsigned)l3 << 16);

    unsigned short* row = Ap + m * KP;
    *(uint2*)(row + k)        = hv;
    *(uint2*)(row + 512 + k)  = lv;
    *(uint2*)(row + 1024 + k) = hv;
}

__global__ void pack_w_kernel(const float* __restrict__ W,
                              unsigned short* __restrict__ Wp, int N)
{
    const int idx = blockIdx.x * blockDim.x + threadIdx.x;
    if (idx >= N * 512) return;
    const int n = idx / 512;
    const int k = idx % 512;
    const float v = W[(size_t)k * N + n];
    unsigned short hi = f2bf(v);
    unsigned short lo = f2bf(v - bf2f(hi));
    unsigned short* row = Wp + (size_t)n * KP;
    row[k]        = hi;
    row[512 + k]  = hi;
    row[1024 + k] = lo;
}

// ---------------------------------------------------------------------------
// bf16 tensor-core GEMM (proven round-8 version): 4-stage cp.async pipeline,
// BM=128, BN=128, BK=32, 256 threads, 8 warps (2m x 4n), warp tile 64x32.
// ---------------------------------------------------------------------------
#define TSTRIDE 40
#define GSTAGES 4
#define GST_HALVES (128 * TSTRIDE)
#define GST_BYTES  (GST_HALVES * 2)
#define GSMEM_TOTAL (GSTAGES * GST_BYTES * 2)

template <bool RELU, bool PACK>
__global__ __launch_bounds__(256, 2)
void bgemm_kernel(const unsigned short* __restrict__ Ap,
                  const unsigned short* __restrict__ Wp,
                  const float* __restrict__ bias,
                  float* __restrict__ Cf,
                  unsigned short* __restrict__ Cp,
                  int N)
{
    extern __shared__ char gsm[];
    unsigned short* As = (unsigned short*)gsm;
    unsigned short* Bs = (unsigned short*)(gsm + GSTAGES * GST_BYTES);

    const int tid  = threadIdx.x;
    const int m0   = blockIdx.y * 128;
    const int n0   = blockIdx.x * 128;
    const int wid  = tid >> 5;
    const int lane = tid & 31;
    const int wm   = wid & 1;
    const int wn   = wid >> 1;

    const int lrow = tid >> 1;
    const int lcol = (tid & 1) * 16;
    const unsigned short* Ag = Ap + (size_t)(m0 + lrow) * KP + lcol;
    const unsigned short* Bg = Wp + (size_t)(n0 + lrow) * KP + lcol;

    const unsigned uA0 = smem_u32(As);
    const unsigned uB0 = smem_u32(Bs);
    const unsigned sa0 = uA0 + (unsigned)(lrow * TSTRIDE + lcol) * 2;
    const unsigned sb0 = uB0 + (unsigned)(lrow * TSTRIDE + lcol) * 2;

    const int aj  = lane >> 3;
    const int ar  = (aj & 1) * 8 + (lane & 7);
    const int akq = (aj >> 1) * 8;

    float acc[4][4][4];
#pragma unroll
    for (int i = 0; i < 4; i++)
#pragma unroll
        for (int j = 0; j < 4; j++)
#pragma unroll
            for (int q = 0; q < 4; q++) acc[i][j][q] = 0.0f;

#define G_ISSUE(it_) do {                                              \
        const int _buf = (it_) & (GSTAGES - 1);                        \
        const int _k0  = (it_) * 32;                                   \
        cp16(sa0 + _buf * GST_BYTES,      Ag + _k0);                   \
        cp16(sa0 + _buf * GST_BYTES + 16, Ag + _k0 + 8);               \
        cp16(sb0 + _buf * GST_BYTES,      Bg + _k0);                   \
        cp16(sb0 + _buf * GST_BYTES + 16, Bg + _k0 + 8);               \
        cp_commit();                                                   \
    } while (0)

    G_ISSUE(0); G_ISSUE(1); G_ISSUE(2);

    const int NITER = KP / 32;   // 48
    for (int it = 0; it < NITER; it++) {
        if (it < NITER - 2)       cp_wait<2>();
        else if (it == NITER - 2) cp_wait<1>();
        else                      cp_wait<0>();
        __syncthreads();
        if (it + 3 < NITER) G_ISSUE(it + 3);

        const int buf = it & (GSTAGES - 1);
        const unsigned uA = uA0 + (unsigned)buf * GST_BYTES;
        const unsigned uB = uB0 + (unsigned)buf * GST_BYTES;

#pragma unroll
        for (int kk = 0; kk < 32; kk += 16) {
            unsigned a[4][4], b[2][4];
#pragma unroll
            for (int mi = 0; mi < 4; mi++)
                ldsm_x4(a[mi][0], a[mi][1], a[mi][2], a[mi][3],
                        uA + (unsigned)((wm * 64 + mi * 16 + ar) * TSTRIDE + kk + akq) * 2);
#pragma unroll
            for (int p = 0; p < 2; p++)
                ldsm_x4(b[p][0], b[p][1], b[p][2], b[p][3],
                        uB + (unsigned)((wn * 32 + p * 16 + ar) * TSTRIDE + kk + akq) * 2);
#pragma unroll
            for (int mi = 0; mi < 4; mi++) {
#pragma unroll
                for (int p = 0; p < 2; p++) {
                    mma_bf16(acc[mi][2*p][0], acc[mi][2*p][1], acc[mi][2*p][2], acc[mi][2*p][3],
                             a[mi][0], a[mi][1], a[mi][2], a[mi][3], b[p][0], b[p][2]);
                    mma_bf16(acc[mi][2*p+1][0], acc[mi][2*p+1][1], acc[mi][2*p+1][2], acc[mi][2*p+1][3],
                             a[mi][0], a[mi][1], a[mi][2], a[mi][3], b[p][1], b[p][3]);
                }
            }
        }
    }
#undef G_ISSUE

    const int quad = lane >> 2;
    const int tq   = lane & 3;
#pragma unroll
    for (int mi = 0; mi < 4; mi++) {
#pragma unroll
        for (int ni = 0; ni < 4; ni++) {
            const int n = n0 + wn * 32 + ni * 8 + tq * 2;
            const float bb0 = bias[n], bb1 = bias[n + 1];
#pragma unroll
            for (int half = 0; half < 2; half++) {
                const int m = m0 + wm * 64 + mi * 16 + quad + half * 8;
                float v0 = acc[mi][ni][half * 2 + 0] + bb0;
                float v1 = acc[mi][ni][half * 2 + 1] + bb1;
                if (RELU) { v0 = fmaxf(v0, 0.f); v1 = fmaxf(v1, 0.f); }
                if (PACK) {
                    unsigned short h0 = f2bf(v0), h1 = f2bf(v1);
                    unsigned short l0 = f2bf(v0 - bf2f(h0));
                    unsigned short l1 = f2bf(v1 - bf2f(h1));
                    unsigned hv = (unsigned)h0 | ((unsigned)h1 << 16);
                    unsigned lv = (unsigned)l0 | ((unsigned)l1 << 16);
                    unsigned short* row = Cp + (size_t)m * KP;
                    *(unsigned*)(row + n)        = hv;
                    *(unsigned*)(row + 512 + n)  = lv;
                    *(unsigned*)(row + 1024 + n) = hv;
                } else {
                    float2 v; v.x = v0; v.y = v1;
                    *(float2*)(Cf + (size_t)m * N + n) = v;
                }
            }
        }
    }
}

// ---------------------------------------------------------------------------
// Persistent recurrence kernel, barrier-free dataflow version.
// Per phase: producers set per-CTA flags after writing their chunk; consumer
// threads 0..15 poll flag j and bulk-copy chunk j (aggregate mbar, count 16).
// ---------------------------------------------------------------------------
#define WS1_STRIDE 1032
#define WS2_STRIDE 520

#define OFF_WS1  0
#define OFF_WS2  (OFF_WS1 + 32 * WS1_STRIDE * 2)     // 66048
#define OFF_ACH  (OFF_WS2 + 64 * WS2_STRIDE * 2)     // 132608 (128B aligned)
#define OFF_H1S  (OFF_ACH + 65536)                   // 198144
#define OFF_B1   (OFF_H1S + 32768)                   // 230912
#define OFF_B2   (OFF_B1 + 32 * 4)                   // 231040
#define OFF_LEN  (OFF_B2 + 64 * 4)                   // 231296
#define OFF_MBAR (OFF_LEN + 32 * 4)                  // 231424
#define SMEM_TOTAL (OFF_MBAR + 4 * 8)                // 231456

__global__ __launch_bounds__(NTHR, 1)
void recurrence_tc(const float* __restrict__ W1h,
                   const float* __restrict__ b1h,
                   const float* __restrict__ W2h,
                   const float* __restrict__ b2h,
                   const int*   __restrict__ lens,
                   float* __restrict__ out)
{
    extern __shared__ char smem[];
    unsigned short* ws1 = (unsigned short*)(smem + OFF_WS1);
    unsigned short* ws2 = (unsigned short*)(smem + OFF_WS2);
    float* b1s = (float*)(smem + OFF_B1);
    float* b2s = (float*)(smem + OFF_B2);
    int*   lns = (int*)(smem + OFF_LEN);
    const float* xs = (const float*)(smem + OFF_ACH);   // xh staging (phase B)

    const unsigned u_ws1 = smem_u32(ws1);
    const unsigned u_ws2 = smem_u32(ws2);
    const unsigned u_ach = smem_u32(smem + OFF_ACH);
    const unsigned u_h1s = smem_u32(smem + OFF_H1S);
    const unsigned u_bar = smem_u32(smem + OFF_MBAR);   // barA, barB

    const int tid  = threadIdx.x;
    const int cta  = blockIdx.x;
    const int wid  = tid >> 5;
    const int lane = tid & 31;
    const int quad = lane >> 2;
    const int tq   = lane & 3;

    const int grp = cta >> 4;
    const int mem = cta & 15;
    const int rA = grp * 32;
    const int cA = mem * 32;
    const int cB = mem * 64;

    const int mh = wid & 1;
    const int nb = wid >> 1;
    const int np = wid >> 1;

    for (int i = tid; i < 1024 * 32; i += NTHR) {
        int k = i >> 5, n = i & 31;
        ws1[n * WS1_STRIDE + k] = f2bf(W1h[(size_t)k * HALF_H + cA + n]);
    }
    for (int i = tid; i < 512 * 64; i += NTHR) {
        int k = i >> 6, n = i & 63;
        ws2[n * WS2_STRIDE + k] = f2bf(W2h[(size_t)k * HIDDEN + cB + n]);
    }
    if (tid < 32) { b1s[tid] = b1h[cA + tid]; lns[tid] = lens[rA + tid]; }
    if (tid < 64) b2s[tid] = b2h[cB + tid];

    if (tid == 0) {
        mbar_init(u_bar + 0, 16);    // barA
        mbar_init(u_bar + 8, 16);    // barB
        g_hflag[grp][mem * 32]  = 0; // reset own flags (replay-safe)
        g_h1flag[grp][mem * 32] = 0;
    }

    // zero own h chunk (zeros are swizzle-invariant)
    {
        unsigned* hz = (unsigned*)g_h_bf16 + (size_t)(grp * 16 + mem) * 1024;
        for (int i = tid; i < 1024; i += NTHR) hz[i] = 0u;
    }

    float hreg[2][4];
#pragma unroll
    for (int b = 0; b < 2; b++)
#pragma unroll
        for (int j = 0; j < 4; j++) hreg[b][j] = 0.0f;

    groupbar(grp);   // flags reset + zeros + mbar inits visible group-wide

    // ldmatrix lane mapping
    const int aj   = lane >> 3;
    const int arow = mh * 16 + (aj & 1) * 8 + (lane & 7);   // 0..31
    const int ku   = aj >> 1;                               // 0/1
    const int swzA = arow & 7;
    const int swzB = arow & 3;
    const int li   = lane & 15;
    const int brow_in = li & 7;
    const int bkq  = (li >> 3) * 8;

    // chunk bases in global (bytes)
    const char* ghg  = (const char*)g_h_bf16  + (size_t)grp * 16 * 4096;
    const char* gh1g = (const char*)g_h1_bf16 + (size_t)grp * 16 * 2048;

    for (int t = 0; t < SEQLEN; t++) {
        const unsigned par = (unsigned)(t & 1);

        // ============ PHASE A: h1 = relu(h @ W1h + b1) ============
        if (tid < 16) {
            while (g_hflag[grp][tid * 32] < (unsigned)t) { }
            mbar_expect(u_bar + 0, 4096);
            bulk_g2s(u_ach + (unsigned)tid * 4096, ghg + (size_t)tid * 4096,
                     4096, u_bar + 0);
        }
        mbar_wait(u_bar + 0, par);

        float ca[4] = {0.f, 0.f, 0.f, 0.f};
#pragma unroll 8
        for (int kk = 0; kk < 1024; kk += 16) {
            const int c  = kk >> 6;
            const int lu = ((kk & 63) >> 3) + ku;
            unsigned a0, a1, a2, a3, b0, b1;
            ldsm_x4(a0, a1, a2, a3,
                    u_ach + (unsigned)(c * 4096 + arow * 128 + ((lu ^ swzA) << 4)));
            ldsm_x2(b0, b1, u_ws1 + (unsigned)((nb * 8 + brow_in) * WS1_STRIDE + kk + bkq) * 2);
            mma_bf16(ca[0], ca[1], ca[2], ca[3], a0, a1, a2, a3, b0, b1);
        }
        {
            // write own h1 chunk: [32 rows][32 cols], unit u = nb, swizzle u^(r&3)
            const int n = nb * 8 + tq * 2;
            const int m0w = mh * 16 + quad;
            float v0 = fmaxf(ca[0] + b1s[n], 0.f);
            float v1 = fmaxf(ca[1] + b1s[n + 1], 0.f);
            float v2 = fmaxf(ca[2] + b1s[n], 0.f);
            float v3 = fmaxf(ca[3] + b1s[n + 1], 0.f);
            unsigned short* chunk = g_h1_bf16 + (size_t)(grp * 16 + mem) * 1024;
            const int r0 = m0w, r1 = m0w + 8;
            *(unsigned*)(chunk + r0 * 32 + ((nb ^ (r0 & 3)) << 3) + tq * 2) = pack_bf16(v0, v1);
            *(unsigned*)(chunk + r1 * 32 + ((nb ^ (r1 & 3)) << 3) + tq * 2) = pack_bf16(v2, v3);
        }
        __threadfence();
        __syncthreads();
        if (tid == 0) g_h1flag[grp][mem * 32] = (unsigned)(t + 1);

        // ============ PHASE B: h = tanh(xh + h1 @ W2h + b2) ============
        if (tid < 16) {
            while (g_h1flag[grp][tid * 32] < (unsigned)(t + 1)) { }
            mbar_expect(u_bar + 8, 2048);
            bulk_g2s(u_h1s + (unsigned)tid * 2048, gh1g + (size_t)tid * 2048,
                     2048, u_bar + 8);
        }
        // xh prefetch into (now idle) ach region: 32 rows x 64 cols f32 = 8KB
#pragma unroll
        for (int j = 0; j < 2; j++) {
            const int lin = tid * 2 + j;
            const int row = lin >> 4;
            const int u   = lin & 15;
            cp16(u_ach + (unsigned)lin * 16,
                 out + ((size_t)(rA + row) * SEQLEN + t) * HIDDEN + cB + u * 4);
        }
        cp_commit();

        mbar_wait(u_bar + 8, par);

        float cb[2][4];
#pragma unroll
        for (int b = 0; b < 2; b++)
#pragma unroll
            for (int j = 0; j < 4; j++) cb[b][j] = 0.f;

#pragma unroll 8
        for (int kk = 0; kk < 512; kk += 16) {
            const int c  = kk >> 5;
            const int lu = ((kk & 31) >> 3) + ku;
            unsigned a0, a1, a2, a3;
            ldsm_x4(a0, a1, a2, a3,
                    u_h1s + (unsigned)(c * 2048 + arow * 64 + ((lu ^ swzB) << 4)));
#pragma unroll
            for (int b = 0; b < 2; b++) {
                unsigned b0, b1;
                ldsm_x2(b0, b1, u_ws2 + (unsigned)((np * 16 + b * 8 + brow_in) * WS2_STRIDE + kk + bkq) * 2);
                mma_bf16(cb[b][0], cb[b][1], cb[b][2], cb[b][3], a0, a1, a2, a3, b0, b1);
            }
        }

        cp_wait<0>();
        __syncthreads();     // xs fully staged

#pragma unroll
        for (int b = 0; b < 2; b++) {
            const int n = np * 16 + b * 8 + tq * 2;     // local col in 64
            const int u = np * 2 + b;                   // 16B unit 0..7
            const float bb0 = b2s[n], bb1 = b2s[n + 1];
#pragma unroll
            for (int half = 0; half < 2; half++) {
                const int m = mh * 16 + quad + half * 8;
                const int bat = rA + m;
                const int col = cB + n;
                const size_t oidx = ((size_t)bat * SEQLEN + t) * HIDDEN + col;
                float2 xh = *(const float2*)(xs + m * 64 + n);
                float nv0 = tanhf(xh.x + cb[b][half * 2 + 0] + bb0);
                float nv1 = tanhf(xh.y + cb[b][half * 2 + 1] + bb1);
                bool ok = t < lns[m];
                float h0 = ok ? nv0 : hreg[b][half * 2 + 0];
                float h1 = ok ? nv1 : hreg[b][half * 2 + 1];
                hreg[b][half * 2 + 0] = h0;
                hreg[b][half * 2 + 1] = h1;
                float2 hv; hv.x = h0; hv.y = h1;
                *(float2*)(out + oidx) = hv;
                // own h chunk: [32 rows][64 cols], unit u, swizzle u^(r&7)
                unsigned short* chunk = g_h_bf16 + (size_t)(grp * 16 + mem) * 2048;
                *(unsigned*)(chunk + m * 64 + ((u ^ (m & 7)) << 3) + tq * 2) = pack_bf16(h0, h1);
            }
        }
        __threadfence();
        __syncthreads();
        if (tid == 0) g_hflag[grp][mem * 32] = (unsigned)(t + 1);
    }
}

// ---------------------------------------------------------------------------
extern "C" void kernel_launch(void* const* d_in, const int* in_sizes, int n_in,
                              void* d_out, int out_size)
{
    const float* seq  = (const float*)d_in[0];
    const int*   lens = (const int*)  d_in[1];
    const float* w1x  = (const float*)d_in[2];
    const float* b1x  = (const float*)d_in[3];
    const float* w2x  = (const float*)d_in[4];
    const float* b2x  = (const float*)d_in[5];
    const float* w1h  = (const float*)d_in[6];
    const float* b1h  = (const float*)d_in[7];
    const float* w2h  = (const float*)d_in[8];
    const float* b2h  = (const float*)d_in[9];
    float* out = (float*)d_out;

    unsigned short *a1p, *hidp, *w1xp, *w2xp;
    cudaGetSymbolAddress((void**)&a1p,  g_a1p);
    cudaGetSymbolAddress((void**)&hidp, g_hidp);
    cudaGetSymbolAddress((void**)&w1xp, g_w1xp);
    cudaGetSymbolAddress((void**)&w2xp, g_w2xp);

    static bool attr_set = false;
    if (!attr_set) {
        cudaFuncSetAttribute(recurrence_tc,
                             cudaFuncAttributeMaxDynamicSharedMemorySize, SMEM_TOTAL);
        cudaFuncSetAttribute(bgemm_kernel<true, true>,
                             cudaFuncAttributeMaxDynamicSharedMemorySize, GSMEM_TOTAL);
        cudaFuncSetAttribute(bgemm_kernel<false, false>,
                             cudaFuncAttributeMaxDynamicSharedMemorySize, GSMEM_TOTAL);
        attr_set = true;
    }

    // Pack operands (hi/lo split)
    pack_a_kernel<<<(NTOK * EMB / 4) / 256, 256>>>(seq, a1p);
    pack_w_kernel<<<(HALF_H * 512 + 255) / 256, 256>>>(w1x, w1xp, HALF_H);
    pack_w_kernel<<<(HIDDEN * 512 + 255) / 256, 256>>>(w2x, w2xp, HIDDEN);

    // K1: hidp = pack(relu(seq @ w1x + b1x))
    bgemm_kernel<true, true><<<dim3(HALF_H / 128, NTOK / 128), 256, GSMEM_TOTAL>>>(
        a1p, w1xp, b1x, nullptr, hidp, HALF_H);

    // K2: out = hid @ w2x + b2x   (xh)
    bgemm_kernel<false, false><<<dim3(HIDDEN / 128, NTOK / 128), 256, GSMEM_TOTAL>>>(
        hidp, w2xp, b2x, out, nullptr, HIDDEN);

    // K3: persistent recurrence, barrier-free dataflow sync
    recurrence_tc<<<NCTA, NTHR, SMEM_TOTAL>>>(w1h, b1h, w2h, b2h, lens, out);
}